// round 15
// baseline (speedup 1.0000x reference)
#include <cuda_runtime.h>

#define M 8192
#define LOG2E 1.4426950408889634f
#define NND 16                     // Chebyshev nodes (I_16(~1.5) ~ 1e-14: exact in fp32)
#define PI_F 3.14159265358979f
#define NROWS (3 * M)              // 24576 total matvec rows
#define GRID 760                   // 5 blocks/SM x 152 SMs
#define NEVAL 64                   // eval role blocks (128 outputs each)

// Scratch (no allocations; counters self-clean each run for graph replay)
__device__ float g_a[M];           // a_i = q_i * LOG2E / 32 (log2-domain slope)
__device__ float g_k[M];
__device__ float g_v[M];
__device__ float g_anode[NND];     // Chebyshev nodes over [amin, amax]
__device__ float g_wnode[NND];     // barycentric weights
__device__ float g_fn[NND];        // f(a_n) = sum_j 2^(a_n k_j) v_j
__device__ float g_gn[NND];        // g(a_n) = sum_j 2^(a_n k_j)
__device__ int   g_work;           // row work counter (0..NROWS)
__device__ int   g_fin;            // blocks done streaming (target GRID)
__device__ int   g_ndone;          // node blocks done (target NND)
__device__ int   g_edone;          // eval blocks done (target NEVAL)

__device__ __forceinline__ float ex2f(float x) {
    float y;
    asm("ex2.approx.ftz.f32 %0, %1;" : "=f"(y) : "f"(x));
    return y;
}

__device__ __forceinline__ float rcpf(float x) {
    float y;
    asm("rcp.approx.ftz.f32 %0, %1;" : "=f"(y) : "f"(x));
    return y;
}

// ---------------------------------------------------------------------------
// Single persistent kernel, 760 blocks x 256 threads (all resident):
//
// Phase 1 (all blocks): q/k/v matvec rows pulled 1-at-a-time from an atomic
//   counter (R13 proven: DRAM=86.5%). Inner loop frozen (8x float4, __ldcs).
// Phase 2 (post-drain second roles, zero occupancy cost since every block
//   is already resident):
//     bids 0..15  : wait g_fin==GRID (~drain time), then Chebyshev node n:
//                   [amin,amax] of g_a, node/weight, f_n/g_n sums.
//     bids 16..79 : wait g_ndone==NND, barycentric-evaluate 128 outputs.
//     others      : exit immediately (frees slots for <=20 late blocks,
//                   guaranteeing g_fin reaches GRID -> no deadlock).
//   Last eval block resets all counters for the next graph replay.
// ---------------------------------------------------------------------------
__global__ __launch_bounds__(256) void fused_kernel(
    const float* __restrict__ x,
    const float* __restrict__ Wq, const float* __restrict__ bq,
    const float* __restrict__ Wk, const float* __restrict__ bk,
    const float* __restrict__ Wv, const float* __restrict__ bv,
    float* __restrict__ out)
{
    __shared__ float4 xs[M / 4];   // 32 KB
    __shared__ float red[2][8];
    __shared__ int s_id[2];

    const int t = threadIdx.x;
    const int lane = t & 31, w = t >> 5;
    const int bid = blockIdx.x;

    // ---------------- Phase 1: streaming matvec (FROZEN R13 shape) --------
    const float4* x4 = (const float4*)x;
    #pragma unroll
    for (int i = 0; i < 8; i++) xs[t + i * 256] = x4[t + i * 256];

    if (t == 0) s_id[0] = atomicAdd(&g_work, 1);
    __syncthreads();

    int p = 0;
    #pragma unroll 1
    for (int it = 0; ; it++) {
        const int id = s_id[it & 1];
        if (id >= NROWS) break;

        if (t == 0) s_id[(it + 1) & 1] = atomicAdd(&g_work, 1);

        const int mat = id >> 13;          // 0=q, 1=k, 2=v
        const int row = id & (M - 1);
        const float* W = (mat == 0) ? Wq : (mat == 1) ? Wk : Wv;
        const float4* Wrow = (const float4*)(W + (size_t)row * M);

        float acc = 0.0f;
        #pragma unroll
        for (int s = 0; s < 8; s++) {
            float4 wv = __ldcs(Wrow + t + s * 256);
            float4 xv = xs[t + s * 256];
            acc += wv.x * xv.x + wv.y * xv.y + wv.z * xv.z + wv.w * xv.w;
        }

        #pragma unroll
        for (int o = 16; o > 0; o >>= 1)
            acc += __shfl_xor_sync(0xffffffffu, acc, o);
        if (lane == 0) red[p][w] = acc;
        __syncthreads();

        if (t == 0) {
            float s = 0.0f;
            #pragma unroll
            for (int i = 0; i < 8; i++) s += red[p][i];
            if (mat == 0)      g_a[row] = (s + bq[row]) * (LOG2E / 32.0f);
            else if (mat == 1) g_k[row] = s + bk[row];
            else               g_v[row] = s + bv[row];
        }
        p ^= 1;
    }

    __threadfence();
    if (t == 0) atomicAdd(&g_fin, 1);

    if (bid >= NND + NEVAL) return;        // free slots for late blocks

    // ---------------- Phase 2a: node sums (bids 0..NND-1) -----------------
    if (bid < NND) {
        __shared__ float rmin[8], rmax[8], redF[8], redG[8];
        __shared__ float s_an;
        const int n = bid;

        if (t == 0) {
            while (*(volatile int*)&g_fin < GRID) __nanosleep(64);
        }
        __syncthreads();
        __threadfence();

        float mn = 1e30f, mx = -1e30f;
        #pragma unroll
        for (int i = 0; i < M / 256; i++) {
            float v = g_a[t + i * 256];
            mn = fminf(mn, v);
            mx = fmaxf(mx, v);
        }
        #pragma unroll
        for (int o = 16; o > 0; o >>= 1) {
            mn = fminf(mn, __shfl_xor_sync(0xffffffffu, mn, o));
            mx = fmaxf(mx, __shfl_xor_sync(0xffffffffu, mx, o));
        }
        if (lane == 0) { rmin[w] = mn; rmax[w] = mx; }
        __syncthreads();

        if (t == 0) {
            float amin = rmin[0], amax = rmax[0];
            #pragma unroll
            for (int i = 1; i < 8; i++) {
                amin = fminf(amin, rmin[i]);
                amax = fmaxf(amax, rmax[i]);
            }
            const float mid  = 0.5f * (amin + amax);
            const float half = 0.5f * (amax - amin);
            const float th = (2.0f * n + 1.0f) * (PI_F / (2.0f * NND));
            const float an = mid + half * cosf(th);
            s_an = an;
            g_anode[n] = an;
            g_wnode[n] = ((n & 1) ? -1.0f : 1.0f) * sinf(th);
        }
        __syncthreads();
        const float an = s_an;

        float fs = 0.0f, gs = 0.0f;
        #pragma unroll
        for (int i = 0; i < M / 256; i++) {
            const int j = t + i * 256;
            float e = ex2f(an * g_k[j]);
            gs += e;
            fs = fmaf(e, g_v[j], fs);
        }
        #pragma unroll
        for (int o = 16; o > 0; o >>= 1) {
            fs += __shfl_xor_sync(0xffffffffu, fs, o);
            gs += __shfl_xor_sync(0xffffffffu, gs, o);
        }
        if (lane == 0) { redF[w] = fs; redG[w] = gs; }
        __syncthreads();
        if (t == 0) {
            float f = 0.0f, g = 0.0f;
            #pragma unroll
            for (int i = 0; i < 8; i++) { f += redF[i]; g += redG[i]; }
            g_fn[n] = f;
            g_gn[n] = g;
            __threadfence();
            atomicAdd(&g_ndone, 1);
        }
        return;
    }

    // ---------------- Phase 2b: barycentric eval (bids NND..NND+63) -------
    {
        __shared__ float san[NND], swn[NND], sfn[NND], sgn[NND];

        if (t == 0) {
            while (*(volatile int*)&g_ndone < NND) __nanosleep(64);
        }
        __syncthreads();
        __threadfence();

        if (t < NND) {
            san[t] = g_anode[t];
            swn[t] = g_wnode[t];
            sfn[t] = g_fn[t];
            sgn[t] = g_gn[t];
        }
        __syncthreads();

        if (t < 128) {
            const int i = (bid - NND) * 128 + t;
            const float a = g_a[i];

            float num = 0.0f, den = 0.0f;
            #pragma unroll
            for (int n = 0; n < NND; n++) {
                float d = a - san[n];
                // a at a node: t_n dominates -> limit f_n/g_n
                if (fabsf(d) < 1e-12f) d = (d >= 0.0f) ? 1e-12f : -1e-12f;
                float r = swn[n] * rcpf(d);
                num = fmaf(r, sfn[n], num);
                den = fmaf(r, sgn[n], den);
            }
            out[i] = num / den;
        }

        __syncthreads();
        if (t == 0) {
            __threadfence();
            if (atomicAdd(&g_edone, 1) == NEVAL - 1) {
                g_work = 0;
                g_fin = 0;
                g_ndone = 0;
                g_edone = 0;
            }
        }
    }
}

// ---------------------------------------------------------------------------
extern "C" void kernel_launch(void* const* d_in, const int* in_sizes, int n_in,
                              void* d_out, int out_size)
{
    const float* x  = (const float*)d_in[0];
    const float* Wq = (const float*)d_in[1];
    const float* bq = (const float*)d_in[2];
    const float* Wk = (const float*)d_in[3];
    const float* bk = (const float*)d_in[4];
    const float* Wv = (const float*)d_in[5];
    const float* bv = (const float*)d_in[6];
    float* out = (float*)d_out;

    fused_kernel<<<GRID, 256>>>(x, Wq, bq, Wk, bk, Wv, bv, out);
}

// round 16
// speedup vs baseline: 1.1491x; 1.1491x over previous
#include <cuda_runtime.h>

#define M 8192
#define LOG2E 1.4426950408889634f
#define NND 16                     // Chebyshev nodes (I_16(~1.5) ~ 1e-14: exact in fp32)
#define PI_F 3.14159265358979f
#define NROWS (3 * M)              // 24576 total matvec rows
#define GRID 760                   // >= 5 blocks/SM * 152 SMs (residency cap)

// Scratch (no allocations; counters self-clean each run for graph replay)
__device__ float g_a[M];           // a_i = q_i * LOG2E / 32 (log2-domain slope)
__device__ float g_k[M];
__device__ float g_v[M];
__device__ float g_anode[NND];     // Chebyshev nodes over [amin, amax]
__device__ float g_wnode[NND];     // barycentric weights
__device__ float g_fn[NND];        // f(a_n) = sum_j 2^(a_n k_j) v_j
__device__ float g_gn[NND];        // g(a_n) = sum_j 2^(a_n k_j)
__device__ int   g_work;           // row work counter (0..NROWS)
__device__ int   g_fin;            // finished qkv blocks (target GRID)

__device__ __forceinline__ float ex2f(float x) {
    float y;
    asm("ex2.approx.ftz.f32 %0, %1;" : "=f"(y) : "f"(x));
    return y;
}

__device__ __forceinline__ float rcpf(float x) {
    float y;
    asm("rcp.approx.ftz.f32 %0, %1;" : "=f"(y) : "f"(x));
    return y;
}

// ---------------------------------------------------------------------------
// Kernel 1: q,k,v matvecs — persistent blocks pulling SINGLE rows from an
// atomic counter (R13 EXACT revert: measured DRAM=86.5%, 118.0us, regs=46).
// 1-row granularity shrinks the end-of-kernel drain to ~3us; next row id
// prefetched during current row's compute; red[] double-buffered -> one
// barrier per row. NOTHING else may share this kernel (R14 lesson: extra
// same-kernel code reallocates registers and collapses the load MLP).
// ---------------------------------------------------------------------------
__global__ __launch_bounds__(256) void qkv_kernel(
    const float* __restrict__ x,
    const float* __restrict__ Wq, const float* __restrict__ bq,
    const float* __restrict__ Wk, const float* __restrict__ bk,
    const float* __restrict__ Wv, const float* __restrict__ bv)
{
    __shared__ float4 xs[M / 4];   // 32 KB
    __shared__ float red[2][8];
    __shared__ int s_id[2];

    const int t = threadIdx.x;
    const int lane = t & 31, w = t >> 5;

    const float4* x4 = (const float4*)x;
    #pragma unroll
    for (int i = 0; i < 8; i++) xs[t + i * 256] = x4[t + i * 256];

    if (t == 0) s_id[0] = atomicAdd(&g_work, 1);
    __syncthreads();

    int p = 0;
    #pragma unroll 1
    for (int it = 0; ; it++) {
        const int id = s_id[it & 1];
        if (id >= NROWS) break;

        // prefetch next row id (overlaps with this row's loads/compute)
        if (t == 0) s_id[(it + 1) & 1] = atomicAdd(&g_work, 1);

        const int mat = id >> 13;          // 0=q, 1=k, 2=v
        const int row = id & (M - 1);
        const float* W = (mat == 0) ? Wq : (mat == 1) ? Wk : Wv;
        const float4* Wrow = (const float4*)(W + (size_t)row * M);

        float acc = 0.0f;
        #pragma unroll
        for (int s = 0; s < 8; s++) {
            float4 wv = __ldcs(Wrow + t + s * 256);
            float4 xv = xs[t + s * 256];
            acc += wv.x * xv.x + wv.y * xv.y + wv.z * xv.z + wv.w * xv.w;
        }

        #pragma unroll
        for (int o = 16; o > 0; o >>= 1)
            acc += __shfl_xor_sync(0xffffffffu, acc, o);
        if (lane == 0) red[p][w] = acc;
        __syncthreads();   // red[p] ready; s_id for next iter ready

        if (t == 0) {
            float s = 0.0f;
            #pragma unroll
            for (int i = 0; i < 8; i++) s += red[p][i];
            if (mat == 0)      g_a[row] = (s + bq[row]) * (LOG2E / 32.0f);
            else if (mat == 1) g_k[row] = s + bk[row];
            else               g_v[row] = s + bv[row];
        }
        p ^= 1;            // next iter writes the other red buffer (no WAR)
    }

    // last block out resets counters for the next graph replay
    if (t == 0) {
        __threadfence();
        if (atomicAdd(&g_fin, 1) == GRID - 1) {
            g_work = 0;
            g_fin = 0;
        }
    }
}

// ---------------------------------------------------------------------------
// Kernel 2: fused nodes + node sums (R10/R13 shape). NND blocks x 256 thr.
// Each block computes [amin,amax] of g_a (L2-hot), derives its Chebyshev
// node/weight analytically, then f_n = sum_j 2^(a_n k_j) v_j and
// g_n = sum_j 2^(a_n k_j).
// ---------------------------------------------------------------------------
__global__ __launch_bounds__(256) void nodesum_kernel()
{
    __shared__ float rmin[8], rmax[8], redF[8], redG[8];
    __shared__ float s_an;
    const int t = threadIdx.x;
    const int n = blockIdx.x;

    float mn = 1e30f, mx = -1e30f;
    #pragma unroll
    for (int i = 0; i < M / 256; i++) {
        float v = g_a[t + i * 256];
        mn = fminf(mn, v);
        mx = fmaxf(mx, v);
    }
    #pragma unroll
    for (int o = 16; o > 0; o >>= 1) {
        mn = fminf(mn, __shfl_xor_sync(0xffffffffu, mn, o));
        mx = fmaxf(mx, __shfl_xor_sync(0xffffffffu, mx, o));
    }
    if ((t & 31) == 0) { rmin[t >> 5] = mn; rmax[t >> 5] = mx; }
    __syncthreads();

    if (t == 0) {
        float amin = rmin[0], amax = rmax[0];
        #pragma unroll
        for (int i = 1; i < 8; i++) {
            amin = fminf(amin, rmin[i]);
            amax = fmaxf(amax, rmax[i]);
        }
        const float mid  = 0.5f * (amin + amax);
        const float half = 0.5f * (amax - amin);
        const float th = (2.0f * n + 1.0f) * (PI_F / (2.0f * NND));
        const float an = mid + half * cosf(th);
        s_an = an;
        g_anode[n] = an;
        g_wnode[n] = ((n & 1) ? -1.0f : 1.0f) * sinf(th);
    }
    __syncthreads();
    const float an = s_an;

    float fs = 0.0f, gs = 0.0f;
    #pragma unroll
    for (int i = 0; i < M / 256; i++) {
        const int j = t + i * 256;
        float e = ex2f(an * g_k[j]);
        gs += e;
        fs = fmaf(e, g_v[j], fs);
    }
    #pragma unroll
    for (int o = 16; o > 0; o >>= 1) {
        fs += __shfl_xor_sync(0xffffffffu, fs, o);
        gs += __shfl_xor_sync(0xffffffffu, gs, o);
    }
    if ((t & 31) == 0) { redF[t >> 5] = fs; redG[t >> 5] = gs; }
    __syncthreads();
    if (t == 0) {
        float f = 0.0f, g = 0.0f;
        #pragma unroll
        for (int i = 0; i < 8; i++) { f += redF[i]; g += redG[i]; }
        g_fn[n] = f;
        g_gn[n] = g;
    }
}

// ---------------------------------------------------------------------------
// Kernel 3: barycentric evaluation (R10/R13 shape). 64 blocks x 128 threads.
// out_i = (sum w_n/(a-a_n) f_n) / (sum w_n/(a-a_n) g_n).
// ---------------------------------------------------------------------------
__global__ __launch_bounds__(128) void eval_kernel(float* __restrict__ out)
{
    __shared__ float san[NND], swn[NND], sfn[NND], sgn[NND];
    const int t = threadIdx.x;

    if (t < NND) {
        san[t] = g_anode[t];
        swn[t] = g_wnode[t];
        sfn[t] = g_fn[t];
        sgn[t] = g_gn[t];
    }
    __syncthreads();

    const int i = blockIdx.x * 128 + t;
    const float a = g_a[i];

    float num = 0.0f, den = 0.0f;
    #pragma unroll
    for (int n = 0; n < NND; n++) {
        float d = a - san[n];
        // a coinciding with a node: t_n dominates -> limit f_n/g_n
        if (fabsf(d) < 1e-12f) d = (d >= 0.0f) ? 1e-12f : -1e-12f;
        float r = swn[n] * rcpf(d);
        num = fmaf(r, sfn[n], num);
        den = fmaf(r, sgn[n], den);
    }
    out[i] = num / den;
}

// ---------------------------------------------------------------------------
extern "C" void kernel_launch(void* const* d_in, const int* in_sizes, int n_in,
                              void* d_out, int out_size)
{
    const float* x  = (const float*)d_in[0];
    const float* Wq = (const float*)d_in[1];
    const float* bq = (const float*)d_in[2];
    const float* Wk = (const float*)d_in[3];
    const float* bk = (const float*)d_in[4];
    const float* Wv = (const float*)d_in[5];
    const float* bv = (const float*)d_in[6];
    float* out = (float*)d_out;

    qkv_kernel<<<GRID, 256>>>(x, Wq, bq, Wk, bk, Wv, bv);
    nodesum_kernel<<<NND, 256>>>();
    eval_kernel<<<M / 128, 128>>>(out);
}

// round 17
// speedup vs baseline: 1.1506x; 1.0013x over previous
#include <cuda_runtime.h>

#define M 8192
#define LOG2E 1.4426950408889634f
#define NND 16                     // Chebyshev nodes (I_16(~1.5) ~ 1e-14: exact in fp32)
#define PI_F 3.14159265358979f
#define NROWS (3 * M)              // 24576 total matvec rows
#define GRID 760                   // >= 5 blocks/SM * 152 SMs (residency cap)

// Scratch (no allocations; counters self-clean each run for graph replay)
__device__ float g_a[M];           // a_i = q_i * LOG2E / 32 (log2-domain slope)
__device__ float g_k[M];
__device__ float g_v[M];
__device__ float g_anode[NND];     // Chebyshev nodes over [amin, amax]
__device__ float g_wnode[NND];     // barycentric weights
__device__ float g_fn[NND];        // f(a_n) = sum_j 2^(a_n k_j) v_j
__device__ float g_gn[NND];        // g(a_n) = sum_j 2^(a_n k_j)
__device__ int   g_work;           // row work counter (0..NROWS)
__device__ int   g_fin;            // finished qkv blocks (target GRID)

__device__ __forceinline__ float ex2f(float x) {
    float y;
    asm("ex2.approx.ftz.f32 %0, %1;" : "=f"(y) : "f"(x));
    return y;
}

__device__ __forceinline__ float rcpf(float x) {
    float y;
    asm("rcp.approx.ftz.f32 %0, %1;" : "=f"(y) : "f"(x));
    return y;
}

__device__ __forceinline__ void pdl_launch_dependents() {
    asm volatile("griddepcontrol.launch_dependents;");
}

__device__ __forceinline__ void pdl_wait() {
    asm volatile("griddepcontrol.wait;" ::: "memory");
}

// ---------------------------------------------------------------------------
// Kernel 1: q,k,v matvecs — persistent blocks pulling SINGLE rows from an
// atomic counter (FROZEN R13/R15 shape: DRAM=87.0%, 117.3us, regs=46).
// The only addition vs R15: griddepcontrol.launch_dependents AFTER the work
// loop (first finishing block triggers the PDL tail launch ~3us early,
// during the drain). Nothing inside the loop changed.
// ---------------------------------------------------------------------------
__global__ __launch_bounds__(256) void qkv_kernel(
    const float* __restrict__ x,
    const float* __restrict__ Wq, const float* __restrict__ bq,
    const float* __restrict__ Wk, const float* __restrict__ bk,
    const float* __restrict__ Wv, const float* __restrict__ bv)
{
    __shared__ float4 xs[M / 4];   // 32 KB
    __shared__ float red[2][8];
    __shared__ int s_id[2];

    const int t = threadIdx.x;
    const int lane = t & 31, w = t >> 5;

    const float4* x4 = (const float4*)x;
    #pragma unroll
    for (int i = 0; i < 8; i++) xs[t + i * 256] = x4[t + i * 256];

    if (t == 0) s_id[0] = atomicAdd(&g_work, 1);
    __syncthreads();

    int p = 0;
    #pragma unroll 1
    for (int it = 0; ; it++) {
        const int id = s_id[it & 1];
        if (id >= NROWS) break;

        // prefetch next row id (overlaps with this row's loads/compute)
        if (t == 0) s_id[(it + 1) & 1] = atomicAdd(&g_work, 1);

        const int mat = id >> 13;          // 0=q, 1=k, 2=v
        const int row = id & (M - 1);
        const float* W = (mat == 0) ? Wq : (mat == 1) ? Wk : Wv;
        const float4* Wrow = (const float4*)(W + (size_t)row * M);

        float acc = 0.0f;
        #pragma unroll
        for (int s = 0; s < 8; s++) {
            float4 wv = __ldcs(Wrow + t + s * 256);
            float4 xv = xs[t + s * 256];
            acc += wv.x * xv.x + wv.y * xv.y + wv.z * xv.z + wv.w * xv.w;
        }

        #pragma unroll
        for (int o = 16; o > 0; o >>= 1)
            acc += __shfl_xor_sync(0xffffffffu, acc, o);
        if (lane == 0) red[p][w] = acc;
        __syncthreads();   // red[p] ready; s_id for next iter ready

        if (t == 0) {
            float s = 0.0f;
            #pragma unroll
            for (int i = 0; i < 8; i++) s += red[p][i];
            if (mat == 0)      g_a[row] = (s + bq[row]) * (LOG2E / 32.0f);
            else if (mat == 1) g_k[row] = s + bk[row];
            else               g_v[row] = s + bv[row];
        }
        p ^= 1;            // next iter writes the other red buffer (no WAR)
    }

    // PDL: let the tail kernels launch their prologues during our drain.
    pdl_launch_dependents();

    // last block out resets counters for the next graph replay
    if (t == 0) {
        __threadfence();
        if (atomicAdd(&g_fin, 1) == GRID - 1) {
            g_work = 0;
            g_fin = 0;
        }
    }
}

// ---------------------------------------------------------------------------
// Kernel 2: fused nodes + node sums. NND blocks x 256 threads. PDL secondary:
// trig/node setup runs before griddepcontrol.wait; data reads after.
// ---------------------------------------------------------------------------
__global__ __launch_bounds__(256) void nodesum_kernel()
{
    __shared__ float rmin[8], rmax[8], redF[8], redG[8];
    __shared__ float s_an;
    const int t = threadIdx.x;
    const int n = blockIdx.x;

    // prologue (independent of primary's data): node geometry on unit interval
    float c_th = 0.0f, s_th = 0.0f;
    if (t == 0) {
        const float th = (2.0f * n + 1.0f) * (PI_F / (2.0f * NND));
        c_th = cosf(th);
        s_th = sinf(th);
    }

    pdl_wait();    // primary (qkv) memory now visible

    float mn = 1e30f, mx = -1e30f;
    #pragma unroll
    for (int i = 0; i < M / 256; i++) {
        float v = g_a[t + i * 256];
        mn = fminf(mn, v);
        mx = fmaxf(mx, v);
    }
    #pragma unroll
    for (int o = 16; o > 0; o >>= 1) {
        mn = fminf(mn, __shfl_xor_sync(0xffffffffu, mn, o));
        mx = fmaxf(mx, __shfl_xor_sync(0xffffffffu, mx, o));
    }
    if ((t & 31) == 0) { rmin[t >> 5] = mn; rmax[t >> 5] = mx; }
    __syncthreads();

    if (t == 0) {
        float amin = rmin[0], amax = rmax[0];
        #pragma unroll
        for (int i = 1; i < 8; i++) {
            amin = fminf(amin, rmin[i]);
            amax = fmaxf(amax, rmax[i]);
        }
        const float mid  = 0.5f * (amin + amax);
        const float half = 0.5f * (amax - amin);
        const float an = mid + half * c_th;
        s_an = an;
        g_anode[n] = an;
        g_wnode[n] = ((n & 1) ? -1.0f : 1.0f) * s_th;
    }
    __syncthreads();
    const float an = s_an;

    float fs = 0.0f, gs = 0.0f;
    #pragma unroll
    for (int i = 0; i < M / 256; i++) {
        const int j = t + i * 256;
        float e = ex2f(an * g_k[j]);
        gs += e;
        fs = fmaf(e, g_v[j], fs);
    }
    #pragma unroll
    for (int o = 16; o > 0; o >>= 1) {
        fs += __shfl_xor_sync(0xffffffffu, fs, o);
        gs += __shfl_xor_sync(0xffffffffu, gs, o);
    }
    if ((t & 31) == 0) { redF[t >> 5] = fs; redG[t >> 5] = gs; }
    __syncthreads();
    if (t == 0) {
        float f = 0.0f, g = 0.0f;
        #pragma unroll
        for (int i = 0; i < 8; i++) { f += redF[i]; g += redG[i]; }
        g_fn[n] = f;
        g_gn[n] = g;
    }
    pdl_launch_dependents();
}

// ---------------------------------------------------------------------------
// Kernel 3: barycentric evaluation. 64 blocks x 128 threads. PDL secondary.
// out_i = (sum w_n/(a-a_n) f_n) / (sum w_n/(a-a_n) g_n).
// ---------------------------------------------------------------------------
__global__ __launch_bounds__(128) void eval_kernel(float* __restrict__ out)
{
    __shared__ float san[NND], swn[NND], sfn[NND], sgn[NND];
    const int t = threadIdx.x;

    pdl_wait();    // nodesum results visible

    if (t < NND) {
        san[t] = g_anode[t];
        swn[t] = g_wnode[t];
        sfn[t] = g_fn[t];
        sgn[t] = g_gn[t];
    }
    __syncthreads();

    const int i = blockIdx.x * 128 + t;
    const float a = g_a[i];

    float num = 0.0f, den = 0.0f;
    #pragma unroll
    for (int n = 0; n < NND; n++) {
        float d = a - san[n];
        // a coinciding with a node: t_n dominates -> limit f_n/g_n
        if (fabsf(d) < 1e-12f) d = (d >= 0.0f) ? 1e-12f : -1e-12f;
        float r = swn[n] * rcpf(d);
        num = fmaf(r, sfn[n], num);
        den = fmaf(r, sgn[n], den);
    }
    out[i] = num / den;
}

// ---------------------------------------------------------------------------
extern "C" void kernel_launch(void* const* d_in, const int* in_sizes, int n_in,
                              void* d_out, int out_size)
{
    const float* x  = (const float*)d_in[0];
    const float* Wq = (const float*)d_in[1];
    const float* bq = (const float*)d_in[2];
    const float* Wk = (const float*)d_in[3];
    const float* bk = (const float*)d_in[4];
    const float* Wv = (const float*)d_in[5];
    const float* bv = (const float*)d_in[6];
    float* out = (float*)d_out;

    qkv_kernel<<<GRID, 256>>>(x, Wq, bq, Wk, bk, Wv, bv);

    // PDL launches for the tail: overlap their launch/prologue with qkv drain
    cudaLaunchAttribute attr[1];
    attr[0].id = cudaLaunchAttributeProgrammaticStreamSerialization;
    attr[0].val.programmaticStreamSerializationAllowed = 1;

    {
        cudaLaunchConfig_t cfg = {};
        cfg.gridDim = {NND, 1, 1};
        cfg.blockDim = {256, 1, 1};
        cfg.attrs = attr;
        cfg.numAttrs = 1;
        cudaLaunchKernelEx(&cfg, nodesum_kernel);
    }
    {
        cudaLaunchConfig_t cfg = {};
        cfg.gridDim = {M / 128, 1, 1};
        cfg.blockDim = {128, 1, 1};
        cfg.attrs = attr;
        cfg.numAttrs = 1;
        cudaLaunchKernelEx(&cfg, eval_kernel, (float*)d_out);
    }
}